// round 7
// baseline (speedup 1.0000x reference)
#include <cuda_runtime.h>
#include <math.h>

#define NGRAPH 1024
#define TOPK 32
#define BS 256
#define VPT 4                                // float4 groups per thread in scan
#define CAP2 512                             // per-graph global candidate cap
#define CAP 2048                             // fallback smem cap
#define NEG_MIN (-3.4028234663852886e38f)    // np.finfo(float32).min == -FLT_MAX
#define THR 2.0f                             // prior threshold ~2 sigma

__device__ unsigned g_cand_fl[NGRAPH * CAP2];
__device__ int      g_cand_ix[NGRAPH * CAP2];
__device__ int      g_cand_cnt[NGRAPH];      // zero-init; rank_kernel re-zeros

// Order-preserving float->uint flip: larger float -> larger unsigned.
__device__ __forceinline__ unsigned flipf(float s) {
    unsigned u = __float_as_uint(s);
    return (u & 0x80000000u) ? ~u : (u | 0x80000000u);
}

// ---------------------------------------------------------------------------
// K1: monolithic streaming scan. Each thread owns VPT float4 groups; all 2*VPT
// 128-bit loads are issued before any dependent work (MLP_p1 = 8). Fills
// out[] with NEG_MIN and pushes score > THR candidates to the owning graph's
// global list (graph id loaded only on the ~1% taken path).
// ---------------------------------------------------------------------------
__global__ void __launch_bounds__(BS) scan_kernel(
    const float* __restrict__ scores,
    const int*   __restrict__ cmask,        // bool delivered as int32
    const int*   __restrict__ b32,          // edge_batch (int32 or int64 words)
    float* __restrict__ out,
    int E)
{
    const int  nv   = E >> 2;
    const bool is64 = (b32[(E - 2) | 1] == 0);   // dtype sniff (L1-broadcast)
    const float4 v4 = make_float4(NEG_MIN, NEG_MIN, NEG_MIN, NEG_MIN);

    const float4* sc4 = (const float4*)scores;
    const int4*   cm4 = (const int4*)cmask;
    float4*       o4  = (float4*)out;

    const int base = blockIdx.x * (BS * VPT) + threadIdx.x;

    float4 sc[VPT]; int4 cm[VPT]; bool ok[VPT];
    #pragma unroll
    for (int u = 0; u < VPT; ++u) {
        const int v = base + u * BS;
        ok[u] = v < nv;
        if (ok[u]) { sc[u] = __ldcs(sc4 + v); cm[u] = __ldcs(cm4 + v); }
    }
    #pragma unroll
    for (int u = 0; u < VPT; ++u)
        if (ok[u]) __stcs(o4 + (base + u * BS), v4);
    #pragma unroll
    for (int u = 0; u < VPT; ++u) {
        if (!ok[u]) continue;
        const bool t0 = cm[u].x && sc[u].x > THR;
        const bool t1 = cm[u].y && sc[u].y > THR;
        const bool t2 = cm[u].z && sc[u].z > THR;
        const bool t3 = cm[u].w && sc[u].w > THR;
        if (t0 | t1 | t2 | t3) {
            const int i = (base + u * BS) << 2;
            #pragma unroll
            for (int w = 0; w < 4; ++w) {
                const bool  t = (w == 0) ? t0 : (w == 1) ? t1 : (w == 2) ? t2 : t3;
                const float s = (w == 0) ? sc[u].x : (w == 1) ? sc[u].y : (w == 2) ? sc[u].z : sc[u].w;
                if (t) {
                    const int idx = i + w;
                    const int gph = is64 ? (int)((const long long*)b32)[idx] : b32[idx];
                    const int p   = atomicAdd(&g_cand_cnt[gph], 1);
                    if (p < CAP2) {
                        g_cand_fl[gph * CAP2 + p] = flipf(s);
                        g_cand_ix[gph * CAP2 + p] = idx;
                    }
                }
            }
        }
    }

    // scalar tail (E % 4), handled by block 0
    if (blockIdx.x == 0) {
        for (int i = (nv << 2) + threadIdx.x; i < E; i += BS) {
            const int   c = cmask[i];
            const float s = scores[i];
            out[i] = NEG_MIN;
            if (c && s > THR) {
                const int gph = is64 ? (int)((const long long*)b32)[i] : b32[i];
                const int p   = atomicAdd(&g_cand_cnt[gph], 1);
                if (p < CAP2) {
                    g_cand_fl[gph * CAP2 + p] = flipf(s);
                    g_cand_ix[gph * CAP2 + p] = i;
                }
            }
        }
    }
}

// ---------------------------------------------------------------------------
// K2: per-graph exact top-K ranking (stable tie-break: score desc, index asc)
// from the global candidate list; segmented log-denominator; kept writes.
// Exact radix-select fallback over the raw segment when the list is unusable.
// Resets this graph's counter to 0 at the end (so the next replay starts clean).
// ---------------------------------------------------------------------------
__global__ void __launch_bounds__(BS) rank_kernel(
    const float* __restrict__ logits,
    const float* __restrict__ scores,
    const float* __restrict__ stop,
    const int*   __restrict__ cmask,
    const int*   __restrict__ b32,
    float* __restrict__ out,
    int E)
{
    __shared__ unsigned buf_fl[CAP];
    __shared__ int      buf_ix[CAP];
    __shared__ int      s_kidx[TOPK];
    __shared__ float    s_lv[TOPK];
    __shared__ float    s_ld;
    __shared__ int      seg[2];
    __shared__ int      hist[2048];
    __shared__ int      s_found, s_bin, s_above, s_minix, s_kcnt;
    __shared__ unsigned s_Tf;
    __shared__ int      s_Tix;

    const int g   = blockIdx.x;
    const int tid = threadIdx.x;
    const int cnt = g_cand_cnt[g];

    int kc;
    if (cnt >= TOPK && cnt <= CAP2) {
        // ---- Fast path: rank the global candidate list in smem ----
        for (int j = tid; j < cnt; j += BS) {
            buf_fl[j] = g_cand_fl[g * CAP2 + j];
            buf_ix[j] = g_cand_ix[g * CAP2 + j];
        }
        __syncthreads();
        for (int j = tid; j < cnt; j += BS) {
            const unsigned fj = buf_fl[j];
            const int      ij = buf_ix[j];
            int rk = 0;
            for (int l = 0; l < cnt; ++l) {
                const unsigned fl2 = buf_fl[l];
                rk += (fl2 > fj) || (fl2 == fj && buf_ix[l] < ij);
            }
            if (rk < TOPK) s_kidx[rk] = ij;
        }
        kc = TOPK;
        __syncthreads();
    } else {
        // ---- Fallback: segment bounds + exact 3-level radix select ----
        if (tid < 2) {
            const int target = g + tid;
            int lo = 0;
            if (target == NGRAPH) lo = E;
            else if (target > 0) {
                const bool is64 = (b32[(E - 2) | 1] == 0);
                int hi = E;
                if (is64) {
                    const long long* b = (const long long*)b32;
                    const long long key = (long long)target;
                    while (lo < hi) { int mid = (lo + hi) >> 1; if (b[mid] < key) lo = mid + 1; else hi = mid; }
                } else {
                    while (lo < hi) { int mid = (lo + hi) >> 1; if (b32[mid] < target) lo = mid + 1; else hi = mid; }
                }
            }
            seg[tid] = lo;
        }
        __syncthreads();
        const int s0 = seg[0], s1 = seg[1];

        unsigned prefix = 0, pmask = 0;
        int  above = 0;
        bool keepall = false, have_thr = false;

        for (int lvl = 0; lvl < 3; ++lvl) {
            const int      shift = (lvl == 0) ? 21 : (lvl == 1) ? 10 : 0;
            const unsigned mw    = (lvl == 2) ? 0x3FFu : 0x7FFu;

            for (int j = tid; j < 2048; j += BS) hist[j] = 0;
            if (tid == 0) s_found = 0;
            __syncthreads();

            for (int i = s0 + tid; i < s1; i += BS) {
                if (cmask[i] != 0) {
                    unsigned fl = flipf(scores[i]);
                    if ((fl & pmask) == prefix)
                        atomicAdd(&hist[(fl >> shift) & mw], 1);
                }
            }
            __syncthreads();

            if (tid < 32) {
                const int lane = tid;
                const int Kp   = TOPK - above;
                int cum = 0;
                for (int base = (int)mw; base >= 0; base -= 32) {
                    int bin = base - lane;
                    int c   = (bin >= 0) ? hist[bin] : 0;
                    int incl = c;
                    #pragma unroll
                    for (int off = 1; off < 32; off <<= 1) {
                        int v = __shfl_up_sync(0xffffffffu, incl, off);
                        if (lane >= off) incl += v;
                    }
                    unsigned bal = __ballot_sync(0xffffffffu, cum + incl >= Kp);
                    if (bal) {
                        int first = __ffs(bal) - 1;
                        if (lane == first) { s_bin = bin; s_above = cum + incl - c; s_found = 1; }
                        break;
                    }
                    cum += __shfl_sync(0xffffffffu, incl, 31);
                }
            }
            __syncthreads();

            if (!s_found) { keepall = true; break; }

            const int b = s_bin;
            above  += s_above;
            const int n = hist[b];
            prefix |= ((unsigned)b) << shift;
            pmask  |= mw << shift;
            __syncthreads();

            if (n <= CAP) {
                if (tid == 0) s_kcnt = 0;
                __syncthreads();
                for (int i = s0 + tid; i < s1; i += BS) {
                    if (cmask[i] != 0) {
                        unsigned fl = flipf(scores[i]);
                        if ((fl & pmask) == prefix) {
                            int p = atomicAdd(&s_kcnt, 1);
                            buf_fl[p] = fl; buf_ix[p] = i;
                        }
                    }
                }
                __syncthreads();
                const int nn = s_kcnt;
                const int r  = TOPK - 1 - above;
                for (int j = tid; j < nn; j += BS) {
                    unsigned fj = buf_fl[j]; int ij = buf_ix[j];
                    int rk = 0;
                    for (int l = 0; l < nn; ++l) {
                        unsigned fl2 = buf_fl[l];
                        rk += (fl2 > fj) || (fl2 == fj && buf_ix[l] < ij);
                    }
                    if (rk == r) { s_Tf = fj; s_Tix = ij; }
                }
                have_thr = true;
                __syncthreads();
                break;
            }
        }

        unsigned Tf; int Tix;
        if (keepall)       { Tf = 0u;   Tix = 0x7FFFFFFF; }
        else if (have_thr) { Tf = s_Tf; Tix = s_Tix; }
        else {
            const int m = TOPK - above;
            int last = -1;
            for (int t = 0; t < m; ++t) {
                if (tid == 0) s_minix = 0x7FFFFFFF;
                __syncthreads();
                for (int i = s0 + tid; i < s1; i += BS) {
                    if (cmask[i] != 0 && i > last) {
                        if (flipf(scores[i]) == prefix) atomicMin(&s_minix, i);
                    }
                }
                __syncthreads();
                last = s_minix;
                __syncthreads();
            }
            Tf = prefix; Tix = last;
        }

        if (tid == 0) s_kcnt = 0;
        __syncthreads();
        for (int i = s0 + tid; i < s1; i += BS) {
            if (cmask[i] != 0) {
                unsigned fl = flipf(scores[i]);
                if (fl > Tf || (fl == Tf && i <= Tix)) {
                    int p = atomicAdd(&s_kcnt, 1);
                    if (p < TOPK) s_kidx[p] = i;
                }
            }
        }
        __syncthreads();
        kc = min(s_kcnt, TOPK);
    }

    // ---- Segmented log-denominator over the <=32 kept logits + stop ----
    if (tid < kc) s_lv[tid] = logits[s_kidx[tid]];   // TEMP == 1.0
    __syncthreads();

    if (tid < 32) {
        float v = (tid < kc) ? s_lv[tid] : -INFINITY;
        float mx = v;
        #pragma unroll
        for (int off = 16; off; off >>= 1) mx = fmaxf(mx, __shfl_xor_sync(0xffffffffu, mx, off));
        float e = (tid < kc) ? expf(v - mx) : 0.0f;
        #pragma unroll
        for (int off = 16; off; off >>= 1) e += __shfl_xor_sync(0xffffffffu, e, off);
        if (tid == 0) {
            float st = stop[g];
            float ld;
            if (kc == 0) ld = st;
            else {
                float lse = logf(e) + mx;
                float a = fmaxf(lse, st), b2 = fminf(lse, st);
                ld = a + log1pf(expf(b2 - a));
            }
            s_ld = ld;
        }
    }
    __syncthreads();

    if (tid < kc) out[s_kidx[tid]] = s_lv[tid] - s_ld;

    // Reset this graph's counter for the next (graph-replayed) run.
    if (tid == 0) g_cand_cnt[g] = 0;
}

extern "C" void kernel_launch(void* const* d_in, const int* in_sizes, int n_in,
                              void* d_out, int out_size) {
    const float* logits = (const float*)d_in[0];
    const float* scores = (const float*)d_in[1];
    const float* stop   = (const float*)d_in[2];
    const int*   batch  = (const int*)d_in[3];
    const int*   cmask  = (const int*)d_in[4];
    float* out = (float*)d_out;
    const int E = in_sizes[0];

    const int nv = E >> 2;
    const int nblk = (nv + BS * VPT - 1) / (BS * VPT);
    scan_kernel<<<nblk, BS>>>(scores, cmask, batch, out, E);
    rank_kernel<<<NGRAPH, BS>>>(logits, scores, stop, cmask, batch, out, E);
}

// round 8
// speedup vs baseline: 1.5132x; 1.5132x over previous
#include <cuda_runtime.h>
#include <math.h>

#define NGRAPH 1024
#define TOPK 32
#define BS 256
#define CAP2 512                             // per-graph global candidate cap
#define CAP 2048                             // fallback smem cap
#define NEG_MIN (-3.4028234663852886e38f)    // np.finfo(float32).min == -FLT_MAX
#define THR 2.0f                             // prior threshold ~2 sigma

__device__ unsigned g_cand_fl[NGRAPH * CAP2];
__device__ int      g_cand_ix[NGRAPH * CAP2];
__device__ int      g_cand_cnt[NGRAPH];      // zero-init; rank_kernel re-zeros

// Order-preserving float->uint flip: larger float -> larger unsigned.
__device__ __forceinline__ unsigned flipf(float s) {
    unsigned u = __float_as_uint(s);
    return (u & 0x80000000u) ? ~u : (u | 0x80000000u);
}

// ---------------------------------------------------------------------------
// K1: streaming scan (grid-stride). Fill out[] with NEG_MIN; mask is loaded
// ONLY when some score in the vector exceeds THR (~9% of vectors), cutting
// mask DRAM traffic ~6x. Candidates pushed to the owning graph's global list.
// ---------------------------------------------------------------------------
__global__ void __launch_bounds__(BS) scan_kernel(
    const float* __restrict__ scores,
    const int*   __restrict__ cmask,        // bool delivered as int32
    const int*   __restrict__ b32,          // edge_batch (int32 or int64 words)
    float* __restrict__ out,
    int E)
{
    const int  nv   = E >> 2;
    const int  gid  = blockIdx.x * blockDim.x + threadIdx.x;
    const int  gsz  = gridDim.x * blockDim.x;
    const bool is64 = (b32[(E - 2) | 1] == 0);   // dtype sniff (L1-broadcast)
    const float4 v4 = make_float4(NEG_MIN, NEG_MIN, NEG_MIN, NEG_MIN);

    const float4* sc4 = (const float4*)scores;
    const int4*   cm4 = (const int4*)cmask;
    float4*       o4  = (float4*)out;

    #pragma unroll 4
    for (int v = gid; v < nv; v += gsz) {
        const float4 sc = __ldcs(sc4 + v);
        __stcs(o4 + v, v4);
        const bool t0 = sc.x > THR;
        const bool t1 = sc.y > THR;
        const bool t2 = sc.z > THR;
        const bool t3 = sc.w > THR;
        if (t0 | t1 | t2 | t3) {
            const int4 cm = __ldcs(cm4 + v);    // rare path: mask load
            const int  i  = v << 2;
            #pragma unroll
            for (int w = 0; w < 4; ++w) {
                const bool  t = (w == 0) ? t0 : (w == 1) ? t1 : (w == 2) ? t2 : t3;
                const int   c = (w == 0) ? cm.x : (w == 1) ? cm.y : (w == 2) ? cm.z : cm.w;
                const float s = (w == 0) ? sc.x : (w == 1) ? sc.y : (w == 2) ? sc.z : sc.w;
                if (t && c) {
                    const int idx = i + w;
                    const int gph = is64 ? (int)((const long long*)b32)[idx] : b32[idx];
                    const int p   = atomicAdd(&g_cand_cnt[gph], 1);
                    if (p < CAP2) {
                        g_cand_fl[gph * CAP2 + p] = flipf(s);
                        g_cand_ix[gph * CAP2 + p] = idx;
                    }
                }
            }
        }
    }
    // scalar tail (E % 4)
    for (int i = (nv << 2) + gid; i < E; i += gsz) {
        const float s = scores[i];
        out[i] = NEG_MIN;
        if (s > THR && cmask[i]) {
            const int gph = is64 ? (int)((const long long*)b32)[i] : b32[i];
            const int p   = atomicAdd(&g_cand_cnt[gph], 1);
            if (p < CAP2) {
                g_cand_fl[gph * CAP2 + p] = flipf(s);
                g_cand_ix[gph * CAP2 + p] = i;
            }
        }
    }
}

// ---------------------------------------------------------------------------
// K2: per-graph exact top-K from the candidate list via byte-radix select in
// smem (stable tie-break: score desc, index asc); segmented log-denominator;
// kept writes. Exact gmem radix fallback when the list is unusable.
// ---------------------------------------------------------------------------
__global__ void __launch_bounds__(BS) rank_kernel(
    const float* __restrict__ logits,
    const float* __restrict__ scores,
    const float* __restrict__ stop,
    const int*   __restrict__ cmask,
    const int*   __restrict__ b32,
    float* __restrict__ out,
    int E)
{
    __shared__ unsigned buf_fl[CAP];
    __shared__ int      buf_ix[CAP];
    __shared__ unsigned tb_fl[CAP2];
    __shared__ int      tb_ix[CAP2];
    __shared__ int      s_kidx[TOPK];
    __shared__ float    s_lv[TOPK];
    __shared__ float    s_ld;
    __shared__ int      seg[2];
    __shared__ int      hist[2048];
    __shared__ int      s_found, s_bin, s_above, s_minix, s_kcnt;
    __shared__ unsigned s_Tf;
    __shared__ int      s_Tix;

    const int g   = blockIdx.x;
    const int tid = threadIdx.x;
    const int cnt = g_cand_cnt[g];

    int kc;
    if (cnt >= TOPK && cnt <= CAP2) {
        // ---- Fast path: byte-radix select over the smem candidate list ----
        for (int j = tid; j < cnt; j += BS) {
            buf_fl[j] = g_cand_fl[g * CAP2 + j];
            buf_ix[j] = g_cand_ix[g * CAP2 + j];
        }
        __syncthreads();

        unsigned prefix = 0, pmask = 0;
        int above = 0;
        for (int lvl = 0; lvl < 4; ++lvl) {
            const int shift = 24 - 8 * lvl;
            if (tid < 256) hist[tid] = 0;
            __syncthreads();
            for (int j = tid; j < cnt; j += BS) {
                const unsigned fl = buf_fl[j];
                if ((fl & pmask) == prefix)
                    atomicAdd(&hist[(fl >> shift) & 0xFF], 1);
            }
            __syncthreads();

            if (tid < 32) {
                const int lane = tid;
                const int Kp   = TOPK - above;
                int cum = 0;
                for (int base = 255; base >= 0; base -= 32) {
                    int bin = base - lane;
                    int c   = hist[bin];
                    int incl = c;
                    #pragma unroll
                    for (int off = 1; off < 32; off <<= 1) {
                        int v = __shfl_up_sync(0xffffffffu, incl, off);
                        if (lane >= off) incl += v;
                    }
                    unsigned bal = __ballot_sync(0xffffffffu, cum + incl >= Kp);
                    if (bal) {
                        int first = __ffs(bal) - 1;
                        if (lane == first) { s_bin = bin; s_above = cum + incl - c; }
                        break;
                    }
                    cum += __shfl_sync(0xffffffffu, incl, 31);
                }
            }
            __syncthreads();

            const int b = s_bin;
            const int n = hist[b];
            above  += s_above;
            prefix |= ((unsigned)b) << shift;
            pmask  |= 0xFFu << shift;
            __syncthreads();                    // hist reads done

            if (n <= 64 || lvl == 3) {
                // Collect matching set; exact-rank the (TOPK-1-above)-th
                // within it by (fl desc, idx asc).
                if (tid == 0) s_kcnt = 0;
                __syncthreads();
                for (int j = tid; j < cnt; j += BS) {
                    const unsigned fl = buf_fl[j];
                    if ((fl & pmask) == prefix) {
                        int p = atomicAdd(&s_kcnt, 1);
                        tb_fl[p] = fl; tb_ix[p] = buf_ix[j];
                    }
                }
                __syncthreads();
                const int nn = s_kcnt;
                const int r  = TOPK - 1 - above;
                for (int j = tid; j < nn; j += BS) {
                    const unsigned fj = tb_fl[j];
                    const int      ij = tb_ix[j];
                    int rk = 0;
                    for (int l = 0; l < nn; ++l) {
                        const unsigned fl2 = tb_fl[l];
                        rk += (fl2 > fj) || (fl2 == fj && tb_ix[l] < ij);
                    }
                    if (rk == r) { s_Tf = fj; s_Tix = ij; }
                }
                __syncthreads();
                break;
            }
        }

        // Keep predicate -> exactly TOPK entries.
        const unsigned Tf = s_Tf; const int Tix = s_Tix;
        if (tid == 0) s_kcnt = 0;
        __syncthreads();
        for (int j = tid; j < cnt; j += BS) {
            const unsigned fl = buf_fl[j];
            if (fl > Tf || (fl == Tf && buf_ix[j] <= Tix)) {
                int p = atomicAdd(&s_kcnt, 1);
                s_kidx[p] = buf_ix[j];
            }
        }
        kc = TOPK;
        __syncthreads();
    } else {
        // ---- Fallback: segment bounds + exact 3-level radix over gmem ----
        if (tid < 2) {
            const int target = g + tid;
            int lo = 0;
            if (target == NGRAPH) lo = E;
            else if (target > 0) {
                const bool is64 = (b32[(E - 2) | 1] == 0);
                int hi = E;
                if (is64) {
                    const long long* b = (const long long*)b32;
                    const long long key = (long long)target;
                    while (lo < hi) { int mid = (lo + hi) >> 1; if (b[mid] < key) lo = mid + 1; else hi = mid; }
                } else {
                    while (lo < hi) { int mid = (lo + hi) >> 1; if (b32[mid] < target) lo = mid + 1; else hi = mid; }
                }
            }
            seg[tid] = lo;
        }
        __syncthreads();
        const int s0 = seg[0], s1 = seg[1];

        unsigned prefix = 0, pmask = 0;
        int  above = 0;
        bool keepall = false, have_thr = false;

        for (int lvl = 0; lvl < 3; ++lvl) {
            const int      shift = (lvl == 0) ? 21 : (lvl == 1) ? 10 : 0;
            const unsigned mw    = (lvl == 2) ? 0x3FFu : 0x7FFu;

            for (int j = tid; j < 2048; j += BS) hist[j] = 0;
            if (tid == 0) s_found = 0;
            __syncthreads();

            for (int i = s0 + tid; i < s1; i += BS) {
                if (cmask[i] != 0) {
                    unsigned fl = flipf(scores[i]);
                    if ((fl & pmask) == prefix)
                        atomicAdd(&hist[(fl >> shift) & mw], 1);
                }
            }
            __syncthreads();

            if (tid < 32) {
                const int lane = tid;
                const int Kp   = TOPK - above;
                int cum = 0;
                for (int base = (int)mw; base >= 0; base -= 32) {
                    int bin = base - lane;
                    int c   = (bin >= 0) ? hist[bin] : 0;
                    int incl = c;
                    #pragma unroll
                    for (int off = 1; off < 32; off <<= 1) {
                        int v = __shfl_up_sync(0xffffffffu, incl, off);
                        if (lane >= off) incl += v;
                    }
                    unsigned bal = __ballot_sync(0xffffffffu, cum + incl >= Kp);
                    if (bal) {
                        int first = __ffs(bal) - 1;
                        if (lane == first) { s_bin = bin; s_above = cum + incl - c; s_found = 1; }
                        break;
                    }
                    cum += __shfl_sync(0xffffffffu, incl, 31);
                }
            }
            __syncthreads();

            if (!s_found) { keepall = true; break; }

            const int b = s_bin;
            above  += s_above;
            const int n = hist[b];
            prefix |= ((unsigned)b) << shift;
            pmask  |= mw << shift;
            __syncthreads();

            if (n <= CAP) {
                if (tid == 0) s_kcnt = 0;
                __syncthreads();
                for (int i = s0 + tid; i < s1; i += BS) {
                    if (cmask[i] != 0) {
                        unsigned fl = flipf(scores[i]);
                        if ((fl & pmask) == prefix) {
                            int p = atomicAdd(&s_kcnt, 1);
                            buf_fl[p] = fl; buf_ix[p] = i;
                        }
                    }
                }
                __syncthreads();
                const int nn = s_kcnt;
                const int r  = TOPK - 1 - above;
                for (int j = tid; j < nn; j += BS) {
                    unsigned fj = buf_fl[j]; int ij = buf_ix[j];
                    int rk = 0;
                    for (int l = 0; l < nn; ++l) {
                        unsigned fl2 = buf_fl[l];
                        rk += (fl2 > fj) || (fl2 == fj && buf_ix[l] < ij);
                    }
                    if (rk == r) { s_Tf = fj; s_Tix = ij; }
                }
                have_thr = true;
                __syncthreads();
                break;
            }
        }

        unsigned Tf; int Tix;
        if (keepall)       { Tf = 0u;   Tix = 0x7FFFFFFF; }
        else if (have_thr) { Tf = s_Tf; Tix = s_Tix; }
        else {
            const int m = TOPK - above;
            int last = -1;
            for (int t = 0; t < m; ++t) {
                if (tid == 0) s_minix = 0x7FFFFFFF;
                __syncthreads();
                for (int i = s0 + tid; i < s1; i += BS) {
                    if (cmask[i] != 0 && i > last) {
                        if (flipf(scores[i]) == prefix) atomicMin(&s_minix, i);
                    }
                }
                __syncthreads();
                last = s_minix;
                __syncthreads();
            }
            Tf = prefix; Tix = last;
        }

        if (tid == 0) s_kcnt = 0;
        __syncthreads();
        for (int i = s0 + tid; i < s1; i += BS) {
            if (cmask[i] != 0) {
                unsigned fl = flipf(scores[i]);
                if (fl > Tf || (fl == Tf && i <= Tix)) {
                    int p = atomicAdd(&s_kcnt, 1);
                    if (p < TOPK) s_kidx[p] = i;
                }
            }
        }
        __syncthreads();
        kc = min(s_kcnt, TOPK);
    }

    // ---- Segmented log-denominator over the <=32 kept logits + stop ----
    if (tid < kc) s_lv[tid] = logits[s_kidx[tid]];   // TEMP == 1.0
    __syncthreads();

    if (tid < 32) {
        float v = (tid < kc) ? s_lv[tid] : -INFINITY;
        float mx = v;
        #pragma unroll
        for (int off = 16; off; off >>= 1) mx = fmaxf(mx, __shfl_xor_sync(0xffffffffu, mx, off));
        float e = (tid < kc) ? expf(v - mx) : 0.0f;
        #pragma unroll
        for (int off = 16; off; off >>= 1) e += __shfl_xor_sync(0xffffffffu, e, off);
        if (tid == 0) {
            float st = stop[g];
            float ld;
            if (kc == 0) ld = st;
            else {
                float lse = logf(e) + mx;
                float a = fmaxf(lse, st), b2 = fminf(lse, st);
                ld = a + log1pf(expf(b2 - a));
            }
            s_ld = ld;
        }
    }
    __syncthreads();

    if (tid < kc) out[s_kidx[tid]] = s_lv[tid] - s_ld;

    // Reset this graph's counter for the next (graph-replayed) run.
    if (tid == 0) g_cand_cnt[g] = 0;
}

extern "C" void kernel_launch(void* const* d_in, const int* in_sizes, int n_in,
                              void* d_out, int out_size) {
    const float* logits = (const float*)d_in[0];
    const float* scores = (const float*)d_in[1];
    const float* stop   = (const float*)d_in[2];
    const int*   batch  = (const int*)d_in[3];
    const int*   cmask  = (const int*)d_in[4];
    float* out = (float*)d_out;
    const int E = in_sizes[0];

    scan_kernel<<<2048, BS>>>(scores, cmask, batch, out, E);
    rank_kernel<<<NGRAPH, BS>>>(logits, scores, stop, cmask, batch, out, E);
}